// round 4
// baseline (speedup 1.0000x reference)
#include <cuda_runtime.h>
#include <cstdint>
#include <math.h>

// Problem constants: B=8, K=1024, L=1024, D=1024, O=6, E=128
#define Bb 8
#define Kk 1024
#define Ll 1024
#define Dd 1024
#define Oo 6
#define Ee 128

// ---------------------------------------------------------------------------
// Scratch (device globals: allocation-free, persistent; every element is
// rewritten on every launch so graph replays are deterministic).
// ---------------------------------------------------------------------------
__device__ __align__(16) float g_UsumP[Bb * 8 * Dd];          // k-split partials of sum_k u
__device__ __align__(16) float g_Wv   [Bb * Oo * Dd];         // sum_e W[o,d,e]*Vacc[b,o,e]
__device__ __align__(16) float g_Vacc [Bb * Oo * Ee];         // accumulated v (v0+v1+...)
__device__ __align__(16) float g_vcur [Bb * Oo * Ee];         // v of current iteration
__device__ __align__(16) float g_probs[Bb * Kk * Oo];         // probs of current iteration
__device__ __align__(16) float g_UpP  [Bb * 32 * Oo * Dd];    // per-ktile partials of Up
__device__ int g_mask_u8;

// ---------------------------------------------------------------------------
// K0: detect mask dtype. If the mask is int32 with values 0/1, every byte at
// offset p where p%4 != 0 is zero. If it's uint8 (numpy bool), those bytes are
// ~50% ones. Safe: reads exactly 8192 bytes, in-bounds for both layouts.
// ---------------------------------------------------------------------------
__global__ void k_detect(const unsigned char* __restrict__ m) {
    __shared__ int f;
    int t = threadIdx.x;
    if (t == 0) f = 0;
    __syncthreads();
    int loc = 0;
    for (int p = t; p < Bb * Kk; p += blockDim.x) {
        if ((p & 3) && m[p]) loc = 1;
    }
    if (loc) atomicOr(&f, 1);
    __syncthreads();
    if (t == 0) g_mask_u8 = f;
}

// ---------------------------------------------------------------------------
// K1: Usum partials. grid (Dtiles=8, ksplit=8, B), 128 threads.
// ---------------------------------------------------------------------------
__global__ void k_usum(const float* __restrict__ u) {
    int t  = threadIdx.x;
    int d  = blockIdx.x * 128 + t;
    int ks = blockIdx.y;
    int b  = blockIdx.z;
    const float* p = u + ((size_t)(b * Kk + ks * 128)) * Dd + d;
    float s = 0.f;
#pragma unroll 8
    for (int k = 0; k < 128; k++) s += p[(size_t)k * Dd];
    g_UsumP[(b * 8 + ks) * Dd + d] = s;
}

// ---------------------------------------------------------------------------
// K2: v0 = squash((1/6) * Usum . W).  grid (O, B), 512 threads.
// ---------------------------------------------------------------------------
__global__ __launch_bounds__(512) void k_v0(const float* __restrict__ W) {
    int t = threadIdx.x;
    int o = blockIdx.x, b = blockIdx.y;
    __shared__ float Us[Dd];
    __shared__ float part[4][Ee];
    __shared__ float red[4];

    for (int d = t; d < Dd; d += 512) {
        float s = 0.f;
#pragma unroll
        for (int ks = 0; ks < 8; ks++) s += g_UsumP[(b * 8 + ks) * Dd + d];
        Us[d] = s;
    }
    __syncthreads();

    int e = t & 127, ws = t >> 7;
    const float* Wp = W + (size_t)o * Dd * Ee + e;
    float acc = 0.f;
#pragma unroll 16
    for (int dd = 0; dd < 256; dd++) {
        int d = ws * 256 + dd;
        acc += Us[d] * Wp[(size_t)d * Ee];
    }
    part[ws][e] = acc;
    __syncthreads();

    float v = 0.f;
    if (t < 128) {
        float s = (part[0][t] + part[1][t] + part[2][t] + part[3][t]) * (1.f / 6.f);
        v = s;
        float x = s * s;
#pragma unroll
        for (int sh = 16; sh; sh >>= 1) x += __shfl_xor_sync(0xffffffffu, x, sh);
        if ((t & 31) == 0) red[t >> 5] = x;
    }
    __syncthreads();
    if (t < 128) {
        float sq = red[0] + red[1] + red[2] + red[3];
        float f  = sq / (1.f + sq) / (sqrtf(sq) + 1e-8f);
        g_Vacc[(b * Oo + o) * Ee + t] = f * v;   // Vacc starts as v0
    }
}

// ---------------------------------------------------------------------------
// K3: Wv[b,o,d] = sum_e W[o,d,e] * Vacc[b,o,e].  grid (8, O, B), 128 threads.
// ---------------------------------------------------------------------------
__global__ void k_wv(const float* __restrict__ W) {
    int t = threadIdx.x;
    int d = blockIdx.x * 128 + t;
    int o = blockIdx.y, b = blockIdx.z;
    __shared__ float Vs[Ee];
    if (t < Ee) Vs[t] = g_Vacc[(b * Oo + o) * Ee + t];
    __syncthreads();
    const float* Wp = W + ((size_t)o * Dd + d) * Ee;
    float acc = 0.f;
#pragma unroll 8
    for (int e = 0; e < Ee; e++) acc += Wp[e] * Vs[e];
    g_Wv[(b * Oo + o) * Dd + d] = acc;
}

// ---------------------------------------------------------------------------
// K4: fused logits -> softmax(masked) -> probs -> Up partials.
// grid (K/32=32, B), 256 threads = 8 warps, each warp owns 4 k rows.
// ---------------------------------------------------------------------------
__global__ __launch_bounds__(256) void k_route(const float* __restrict__ u,
                                               const void*  __restrict__ maskp) {
    int t = threadIdx.x;
    int w = t >> 5, lane = t & 31;
    int b  = blockIdx.y;
    int k0 = blockIdx.x * 32;

    __shared__ float Wv_s[Oo * Dd];       // 24 KB
    __shared__ float probs_s[32 * Oo];

    for (int i = t; i < Oo * Dd; i += 256) Wv_s[i] = g_Wv[b * Oo * Dd + i];
    __syncthreads();

    // Phase 1: logits for 4 k per warp
    int kw = k0 + w * 4;
    float lg[4][6];
#pragma unroll
    for (int kk = 0; kk < 4; kk++) {
#pragma unroll
        for (int o = 0; o < 6; o++) lg[kk][o] = 0.f;
    }
    const float* up = u + ((size_t)(b * Kk + kw)) * Dd;
#pragma unroll 8
    for (int j = 0; j < 32; j++) {
        int d = lane + 32 * j;
        float wv[6];
#pragma unroll
        for (int o = 0; o < 6; o++) wv[o] = Wv_s[o * Dd + d];
#pragma unroll
        for (int kk = 0; kk < 4; kk++) {
            float uv = up[(size_t)kk * Dd + d];
#pragma unroll
            for (int o = 0; o < 6; o++) lg[kk][o] += uv * wv[o];
        }
    }
    // butterfly reduce across the warp (all lanes end with full sums)
#pragma unroll
    for (int sh = 16; sh; sh >>= 1) {
#pragma unroll
        for (int kk = 0; kk < 4; kk++) {
#pragma unroll
            for (int o = 0; o < 6; o++)
                lg[kk][o] += __shfl_xor_sync(0xffffffffu, lg[kk][o], sh);
        }
    }

    int u8 = g_mask_u8;
    if (lane == 0) {
#pragma unroll
        for (int kk = 0; kk < 4; kk++) {
            int k = kw + kk;
            bool masked = u8 ? (((const unsigned char*)maskp)[b * Kk + k] != 0)
                             : (((const int*)maskp)[b * Kk + k] != 0);
            float p[6];
            if (masked) {
#pragma unroll
                for (int o = 0; o < 6; o++) p[o] = 1.f / 6.f;
            } else {
                float m = lg[kk][0];
#pragma unroll
                for (int o = 1; o < 6; o++) m = fmaxf(m, lg[kk][o]);
                float s = 0.f;
#pragma unroll
                for (int o = 0; o < 6; o++) { p[o] = expf(lg[kk][o] - m); s += p[o]; }
                float inv = 1.f / s;
#pragma unroll
                for (int o = 0; o < 6; o++) p[o] *= inv;
            }
#pragma unroll
            for (int o = 0; o < 6; o++) probs_s[(w * 4 + kk) * 6 + o] = p[o];
        }
    }
    __syncthreads();

    // coalesced probs store (32 k * 6 o = 192 floats)
    if (t < 192) g_probs[(size_t)(b * Kk + k0) * 6 + t] = probs_s[t];

    // Phase 2: Up partials — thread owns d in {t, t+256, t+512, t+768}
    float acc[6][4];
#pragma unroll
    for (int o = 0; o < 6; o++) {
#pragma unroll
        for (int i = 0; i < 4; i++) acc[o][i] = 0.f;
    }
    const float* ub = u + ((size_t)(b * Kk + k0)) * Dd;
#pragma unroll 4
    for (int kk = 0; kk < 32; kk++) {
        float pv[6];
#pragma unroll
        for (int o = 0; o < 6; o++) pv[o] = probs_s[kk * 6 + o];
#pragma unroll
        for (int i = 0; i < 4; i++) {
            float uv = ub[(size_t)kk * Dd + t + 256 * i];
#pragma unroll
            for (int o = 0; o < 6; o++) acc[o][i] += pv[o] * uv;
        }
    }
    float* upp = g_UpP + ((size_t)(b * 32 + blockIdx.x) * Oo) * Dd;
#pragma unroll
    for (int o = 0; o < 6; o++) {
#pragma unroll
        for (int i = 0; i < 4; i++)
            upp[(size_t)o * Dd + t + 256 * i] = acc[o][i];
    }
}

// ---------------------------------------------------------------------------
// K6: v_i = squash(Up . W); Vacc += v_i; store v_i.  grid (O, B), 512 threads.
// ---------------------------------------------------------------------------
__global__ __launch_bounds__(512) void k_vi(const float* __restrict__ W) {
    int t = threadIdx.x;
    int o = blockIdx.x, b = blockIdx.y;
    __shared__ float Up_s[Dd];
    __shared__ float part[4][Ee];
    __shared__ float red[4];

    for (int d = t; d < Dd; d += 512) {
        float s = 0.f;
#pragma unroll 8
        for (int kt = 0; kt < 32; kt++)
            s += g_UpP[((size_t)(b * 32 + kt) * Oo + o) * Dd + d];
        Up_s[d] = s;
    }
    __syncthreads();

    int e = t & 127, ws = t >> 7;
    const float* Wp = W + (size_t)o * Dd * Ee + e;
    float acc = 0.f;
#pragma unroll 16
    for (int dd = 0; dd < 256; dd++) {
        int d = ws * 256 + dd;
        acc += Up_s[d] * Wp[(size_t)d * Ee];
    }
    part[ws][e] = acc;
    __syncthreads();

    float v = 0.f;
    if (t < 128) {
        float s = part[0][t] + part[1][t] + part[2][t] + part[3][t];
        v = s;
        float x = s * s;
#pragma unroll
        for (int sh = 16; sh; sh >>= 1) x += __shfl_xor_sync(0xffffffffu, x, sh);
        if ((t & 31) == 0) red[t >> 5] = x;
    }
    __syncthreads();
    if (t < 128) {
        float sq = red[0] + red[1] + red[2] + red[3];
        float f  = sq / (1.f + sq) / (sqrtf(sq) + 1e-8f);
        float vv = f * v;
        int idx = (b * Oo + o) * Ee + t;
        g_vcur[idx] = vv;
        g_Vacc[idx] += vv;
    }
}

// ---------------------------------------------------------------------------
// K7: broadcast over L.  out = [outputs_v (B,L,O,E) | probs_c (B,L,K,O)].
// grid 8192 blocks (one per (b,l)), 256 threads, float4 stores.
// ---------------------------------------------------------------------------
__global__ __launch_bounds__(256) void k_bcast(float* __restrict__ out) {
    int t  = threadIdx.x;
    int bl = blockIdx.x;       // b*L + l
    int b  = bl >> 10;

    float4*       ov = reinterpret_cast<float4*>(out);
    const float4* vs = reinterpret_cast<const float4*>(g_vcur);
    if (t < 192) ov[(size_t)bl * 192 + t] = vs[b * 192 + t];   // 768 floats

    float4*       op = reinterpret_cast<float4*>(out + (size_t)Bb * Ll * Oo * Ee);
    const float4* ps = reinterpret_cast<const float4*>(g_probs);
    for (int i = t; i < 1536; i += 256)                         // 6144 floats
        op[(size_t)bl * 1536 + i] = ps[b * 1536 + i];
}

// ---------------------------------------------------------------------------
// Launch
// ---------------------------------------------------------------------------
extern "C" void kernel_launch(void* const* d_in, const int* in_sizes, int n_in,
                              void* d_out, int out_size) {
    const float* u    = (const float*)d_in[0];
    // d_in[1] = context_sequence: unused (only its shape L matters)
    const float* W    = (const float*)d_in[2];
    const void*  mask = d_in[3];
    float* out = (float*)d_out;

    k_detect<<<1, 256>>>((const unsigned char*)mask);
    k_usum  <<<dim3(8, 8, 8), 128>>>(u);
    k_v0    <<<dim3(Oo, Bb), 512>>>(W);

    for (int it = 0; it < 2; it++) {
        k_wv   <<<dim3(8, Oo, Bb), 128>>>(W);
        k_route<<<dim3(Kk / 32, Bb), 256>>>(u, mask);
        k_vi   <<<dim3(Oo, Bb), 512>>>(W);
    }

    k_bcast<<<Bb * Ll, 256>>>(out);
}

// round 7
// speedup vs baseline: 1.0506x; 1.0506x over previous
#include <cuda_runtime.h>
#include <cstdint>
#include <math.h>

// Problem constants: B=8, K=1024, L=1024, D=1024, O=6, E=128
#define Bb 8
#define Kk 1024
#define Ll 1024
#define Dd 1024
#define Oo 6
#define Ee 128

// ---------------------------------------------------------------------------
// Scratch (device globals: allocation-free, persistent; every element is
// rewritten on every launch so graph replays are deterministic).
// ---------------------------------------------------------------------------
__device__ __align__(16) float g_UsumP[Bb * 8 * Dd];          // k-split partials of sum_k u
__device__ __align__(16) float g_Wv   [Bb * Oo * Dd];         // sum_e W[o,d,e]*Vacc[b,o,e]
__device__ __align__(16) float g_Vacc [Bb * Oo * Ee];         // accumulated v (v0+v1+...)
__device__ __align__(16) float g_vcur [Bb * Oo * Ee];         // v of current iteration
__device__ __align__(16) float g_probs[Bb * Kk * Oo];         // probs of current iteration
__device__ __align__(16) float g_UpP  [Bb * 32 * Oo * Dd];    // per-ktile partials of Up
__device__ int g_mask_u8;

// ---------------------------------------------------------------------------
// K0: detect mask dtype (uint8 bool vs int32 0/1). Reads exactly 8192 bytes,
// in-bounds under both layouts.
// ---------------------------------------------------------------------------
__global__ void k_detect(const unsigned char* __restrict__ m) {
    __shared__ int f;
    int t = threadIdx.x;
    if (t == 0) f = 0;
    __syncthreads();
    int loc = 0;
    for (int p = t; p < Bb * Kk; p += blockDim.x) {
        if ((p & 3) && m[p]) loc = 1;
    }
    if (loc) atomicOr(&f, 1);
    __syncthreads();
    if (t == 0) g_mask_u8 = f;
}

// ---------------------------------------------------------------------------
// K1: Usum partials, float4. grid (2, ksplit=8, B), 128 threads.
// Thread owns one float4 d-chunk; loops 128 k rows (coalesced LDG.128).
// ---------------------------------------------------------------------------
__global__ void k_usum(const float* __restrict__ u) {
    int t  = threadIdx.x;
    int d4 = blockIdx.x * 128 + t;      // float4 index in [0,256)
    int ks = blockIdx.y;
    int b  = blockIdx.z;
    const float4* p = reinterpret_cast<const float4*>(u)
                    + ((size_t)(b * Kk + ks * 128)) * 256 + d4;
    float4 s = make_float4(0.f, 0.f, 0.f, 0.f);
#pragma unroll 8
    for (int k = 0; k < 128; k++) {
        float4 v = p[(size_t)k * 256];
        s.x += v.x; s.y += v.y; s.z += v.z; s.w += v.w;
    }
    reinterpret_cast<float4*>(g_UsumP)[(b * 8 + ks) * 256 + d4] = s;
}

// ---------------------------------------------------------------------------
// K2: v0 = squash((1/6) * Usum . W).  grid (O, B), 512 threads.
// W access is coalesced (lanes span consecutive e within a 128B sector).
// ---------------------------------------------------------------------------
__global__ __launch_bounds__(512) void k_v0(const float* __restrict__ W) {
    int t = threadIdx.x;
    int o = blockIdx.x, b = blockIdx.y;
    __shared__ float Us[Dd];
    __shared__ float part[4][Ee];
    __shared__ float red[4];

    for (int d = t; d < Dd; d += 512) {
        float s = 0.f;
#pragma unroll
        for (int ks = 0; ks < 8; ks++) s += g_UsumP[(b * 8 + ks) * Dd + d];
        Us[d] = s;
    }
    __syncthreads();

    int e = t & 127, ws = t >> 7;
    const float* Wp = W + (size_t)o * Dd * Ee + e;
    float acc = 0.f;
#pragma unroll 16
    for (int dd = 0; dd < 256; dd++) {
        int d = ws * 256 + dd;
        acc += Us[d] * Wp[(size_t)d * Ee];
    }
    part[ws][e] = acc;
    __syncthreads();

    float v = 0.f;
    if (t < 128) {
        float s = (part[0][t] + part[1][t] + part[2][t] + part[3][t]) * (1.f / 6.f);
        v = s;
        float x = s * s;
#pragma unroll
        for (int sh = 16; sh; sh >>= 1) x += __shfl_xor_sync(0xffffffffu, x, sh);
        if ((t & 31) == 0) red[t >> 5] = x;
    }
    __syncthreads();
    if (t < 128) {
        float sq = red[0] + red[1] + red[2] + red[3];
        float f  = sq / (1.f + sq) / (sqrtf(sq) + 1e-8f);
        g_Vacc[(b * Oo + o) * Ee + t] = f * v;   // Vacc starts as v0
    }
}

// ---------------------------------------------------------------------------
// K3 (REWRITTEN): Wv[b,o,d] = sum_e W[o,d,e] * Vacc[b,o,e].
// grid (Dd/8=128, Oo), 256 threads = 8 warps, warp w owns d = bx*8+w.
// Warp reads W[o,d,0:128] as 32 consecutive float4 (512B coalesced), dots
// against all 8 b's Vacc vectors held in smem, butterfly-reduces 8 sums.
// W traffic: 3 MB coalesced (was 24 MB uncoalesced per-b).
// ---------------------------------------------------------------------------
__global__ __launch_bounds__(256) void k_wv(const float* __restrict__ W) {
    __shared__ float4 Vs[Bb][32];      // Vacc[b][o][e] for this o: 4 KB
    int t = threadIdx.x, w = t >> 5, lane = t & 31;
    int o = blockIdx.y;

    {
        int b = t >> 5, i = t & 31;    // 256 threads = exactly 8*32
        Vs[b][i] = reinterpret_cast<const float4*>(g_Vacc)[(b * Oo + o) * 32 + i];
    }
    __syncthreads();

    int d = blockIdx.x * 8 + w;
    float4 w4 = reinterpret_cast<const float4*>(W)[((size_t)o * Dd + d) * 32 + lane];

    float acc[8];
#pragma unroll
    for (int b = 0; b < 8; b++) {
        float4 v4 = Vs[b][lane];
        acc[b] = w4.x * v4.x + w4.y * v4.y + w4.z * v4.z + w4.w * v4.w;
    }
#pragma unroll
    for (int sh = 16; sh; sh >>= 1) {
#pragma unroll
        for (int b = 0; b < 8; b++)
            acc[b] += __shfl_xor_sync(0xffffffffu, acc[b], sh);
    }
    if (lane < 8)
        g_Wv[(lane * Oo + o) * Dd + d] = acc[lane];   // b = lane
}

// ---------------------------------------------------------------------------
// K4: fused logits -> softmax(masked) -> probs -> Up partials (float4).
// grid (K/32=32, B), 256 threads = 8 warps, each warp owns 4 k rows.
// ---------------------------------------------------------------------------
__global__ __launch_bounds__(256) void k_route(const float* __restrict__ u,
                                               const void*  __restrict__ maskp) {
    int t = threadIdx.x;
    int w = t >> 5, lane = t & 31;
    int b  = blockIdx.y;
    int k0 = blockIdx.x * 32;

    __shared__ __align__(16) float Wv_s[Oo * Dd];   // 24 KB
    __shared__ float probs_s[32 * Oo];

    {
        float4*       ds = reinterpret_cast<float4*>(Wv_s);
        const float4* ss = reinterpret_cast<const float4*>(g_Wv + (size_t)b * Oo * Dd);
#pragma unroll
        for (int i = 0; i < 6; i++) ds[t + 256 * i] = ss[t + 256 * i];
    }
    __syncthreads();

    // Phase 1: logits for 4 k per warp, float4 over d
    int kw = k0 + w * 4;
    float lg[4][6];
#pragma unroll
    for (int kk = 0; kk < 4; kk++)
#pragma unroll
        for (int o = 0; o < 6; o++) lg[kk][o] = 0.f;

    const float4* up4 = reinterpret_cast<const float4*>(u) + (size_t)(b * Kk + kw) * 256;
    const float4* wv4 = reinterpret_cast<const float4*>(Wv_s);
#pragma unroll
    for (int j = 0; j < 8; j++) {
        int di = j * 32 + lane;                 // float4 index within a d-row
        float4 wv[6];
#pragma unroll
        for (int o = 0; o < 6; o++) wv[o] = wv4[o * 256 + di];
#pragma unroll
        for (int kk = 0; kk < 4; kk++) {
            float4 uv = up4[(size_t)kk * 256 + di];
#pragma unroll
            for (int o = 0; o < 6; o++)
                lg[kk][o] += uv.x * wv[o].x + uv.y * wv[o].y
                           + uv.z * wv[o].z + uv.w * wv[o].w;
        }
    }
#pragma unroll
    for (int sh = 16; sh; sh >>= 1)
#pragma unroll
        for (int kk = 0; kk < 4; kk++)
#pragma unroll
            for (int o = 0; o < 6; o++)
                lg[kk][o] += __shfl_xor_sync(0xffffffffu, lg[kk][o], sh);

    int u8 = g_mask_u8;
    if (lane == 0) {
#pragma unroll
        for (int kk = 0; kk < 4; kk++) {
            int k = kw + kk;
            bool masked = u8 ? (((const unsigned char*)maskp)[b * Kk + k] != 0)
                             : (((const int*)maskp)[b * Kk + k] != 0);
            float p[6];
            if (masked) {
#pragma unroll
                for (int o = 0; o < 6; o++) p[o] = 1.f / 6.f;
            } else {
                float m = lg[kk][0];
#pragma unroll
                for (int o = 1; o < 6; o++) m = fmaxf(m, lg[kk][o]);
                float s = 0.f;
#pragma unroll
                for (int o = 0; o < 6; o++) { p[o] = expf(lg[kk][o] - m); s += p[o]; }
                float inv = 1.f / s;
#pragma unroll
                for (int o = 0; o < 6; o++) p[o] *= inv;
            }
#pragma unroll
            for (int o = 0; o < 6; o++) probs_s[(w * 4 + kk) * 6 + o] = p[o];
        }
    }
    __syncthreads();

    // coalesced probs store (32 k * 6 o = 192 floats)
    if (t < 192) g_probs[(size_t)(b * Kk + k0) * 6 + t] = probs_s[t];

    // Phase 2: Up partials — thread owns float4 d-chunk d4 = t (1024 d total)
    float4 acc4[6];
#pragma unroll
    for (int o = 0; o < 6; o++) acc4[o] = make_float4(0.f, 0.f, 0.f, 0.f);

    const float4* ub4 = reinterpret_cast<const float4*>(u) + (size_t)(b * Kk + k0) * 256;
#pragma unroll 4
    for (int kk = 0; kk < 32; kk++) {
        float4 uv = ub4[(size_t)kk * 256 + t];
        float pv[6];
#pragma unroll
        for (int o = 0; o < 6; o++) pv[o] = probs_s[kk * 6 + o];
#pragma unroll
        for (int o = 0; o < 6; o++) {
            acc4[o].x += pv[o] * uv.x;
            acc4[o].y += pv[o] * uv.y;
            acc4[o].z += pv[o] * uv.z;
            acc4[o].w += pv[o] * uv.w;
        }
    }
    float4* upp4 = reinterpret_cast<float4*>(
        g_UpP + ((size_t)(b * 32 + blockIdx.x) * Oo) * Dd);
#pragma unroll
    for (int o = 0; o < 6; o++) upp4[o * 256 + t] = acc4[o];
}

// ---------------------------------------------------------------------------
// K6: v_i = squash(Up . W); Vacc += v_i; store v_i.  grid (O, B), 512 threads.
// ---------------------------------------------------------------------------
__global__ __launch_bounds__(512) void k_vi(const float* __restrict__ W) {
    int t = threadIdx.x;
    int o = blockIdx.x, b = blockIdx.y;
    __shared__ float Up_s[Dd];
    __shared__ float part[4][Ee];
    __shared__ float red[4];

    for (int d = t; d < Dd; d += 512) {
        float s = 0.f;
#pragma unroll 8
        for (int kt = 0; kt < 32; kt++)
            s += g_UpP[((size_t)(b * 32 + kt) * Oo + o) * Dd + d];
        Up_s[d] = s;
    }
    __syncthreads();

    int e = t & 127, ws = t >> 7;
    const float* Wp = W + (size_t)o * Dd * Ee + e;
    float acc = 0.f;
#pragma unroll 16
    for (int dd = 0; dd < 256; dd++) {
        int d = ws * 256 + dd;
        acc += Up_s[d] * Wp[(size_t)d * Ee];
    }
    part[ws][e] = acc;
    __syncthreads();

    float v = 0.f;
    if (t < 128) {
        float s = part[0][t] + part[1][t] + part[2][t] + part[3][t];
        v = s;
        float x = s * s;
#pragma unroll
        for (int sh = 16; sh; sh >>= 1) x += __shfl_xor_sync(0xffffffffu, x, sh);
        if ((t & 31) == 0) red[t >> 5] = x;
    }
    __syncthreads();
    if (t < 128) {
        float sq = red[0] + red[1] + red[2] + red[3];
        float f  = sq / (1.f + sq) / (sqrtf(sq) + 1e-8f);
        float vv = f * v;
        int idx = (b * Oo + o) * Ee + t;
        g_vcur[idx] = vv;
        g_Vacc[idx] += vv;
    }
}

// ---------------------------------------------------------------------------
// K7: broadcast over L.  out = [outputs_v (B,L,O,E) | probs_c (B,L,K,O)].
// grid 8192 blocks (one per (b,l)), 256 threads, float4 stores.
// ---------------------------------------------------------------------------
__global__ __launch_bounds__(256) void k_bcast(float* __restrict__ out) {
    int t  = threadIdx.x;
    int bl = blockIdx.x;       // b*L + l
    int b  = bl >> 10;

    float4*       ov = reinterpret_cast<float4*>(out);
    const float4* vs = reinterpret_cast<const float4*>(g_vcur);
    if (t < 192) ov[(size_t)bl * 192 + t] = vs[b * 192 + t];   // 768 floats

    float4*       op = reinterpret_cast<float4*>(out + (size_t)Bb * Ll * Oo * Ee);
    const float4* ps = reinterpret_cast<const float4*>(g_probs);
#pragma unroll
    for (int i = 0; i < 6; i++)                                // 6144 floats
        op[(size_t)bl * 1536 + t + 256 * i] = ps[b * 1536 + t + 256 * i];
}

// ---------------------------------------------------------------------------
// Launch
// ---------------------------------------------------------------------------
extern "C" void kernel_launch(void* const* d_in, const int* in_sizes, int n_in,
                              void* d_out, int out_size) {
    const float* u    = (const float*)d_in[0];
    // d_in[1] = context_sequence: unused (only its shape L matters)
    const float* W    = (const float*)d_in[2];
    const void*  mask = d_in[3];
    float* out = (float*)d_out;

    k_detect<<<1, 256>>>((const unsigned char*)mask);
    k_usum  <<<dim3(2, 8, 8), 128>>>(u);
    k_v0    <<<dim3(Oo, Bb), 512>>>(W);

    for (int it = 0; it < 2; it++) {
        k_wv   <<<dim3(Dd / 8, Oo), 256>>>(W);
        k_route<<<dim3(Kk / 32, Bb), 256>>>(u, mask);
        k_vi   <<<dim3(Oo, Bb), 512>>>(W);
    }

    k_bcast<<<Bb * Ll, 256>>>(out);
}

// round 9
// speedup vs baseline: 1.5461x; 1.4717x over previous
#include <cuda_runtime.h>
#include <cstdint>
#include <math.h>

// Problem constants: B=8, K=1024, L=1024, D=1024, O=6, E=128
#define Bb 8
#define Kk 1024
#define Ll 1024
#define Dd 1024
#define Oo 6
#define Ee 128

// ---------------------------------------------------------------------------
// Scratch (device globals: allocation-free, persistent; every element is
// rewritten on every launch so graph replays are deterministic).
// ---------------------------------------------------------------------------
__device__ __align__(16) float g_UsumP[Bb * 8 * Dd];          // k-split partials of sum_k u
__device__ __align__(16) float g_Wv   [Bb * Oo * Dd];         // sum_e W[o,d,e]*Vacc[b,o,e]
__device__ __align__(16) float g_Vacc [Bb * Oo * Ee];         // accumulated v (v0+v1+...)
__device__ __align__(16) float g_vcur [Bb * Oo * Ee];         // v of current iteration
__device__ __align__(16) float g_probs[Bb * Kk * Oo];         // probs of current iteration
__device__ __align__(16) float g_UpP  [Bb * 32 * Oo * Dd];    // per-ktile partials of Up
__device__ int g_mask_u8;

// ---------------------------------------------------------------------------
// K1: Usum partials, float4. grid (2, ksplit=8, B), 128 threads.
// Block (0,0,0) additionally runs the mask-dtype probe (int32 0/1 has zero
// bytes at p%4!=0; uint8 bool does not). Reads exactly 8192 bytes, in-bounds
// under both layouts. Result consumed by k_route in a later launch.
// ---------------------------------------------------------------------------
__global__ void k_usum(const float* __restrict__ u,
                       const unsigned char* __restrict__ m) {
    int t  = threadIdx.x;

    if (blockIdx.x == 0 && blockIdx.y == 0 && blockIdx.z == 0) {
        __shared__ int f;
        if (t == 0) f = 0;
        __syncthreads();
        int loc = 0;
        for (int p = t; p < Bb * Kk; p += blockDim.x)
            if ((p & 3) && m[p]) loc = 1;
        if (loc) atomicOr(&f, 1);
        __syncthreads();
        if (t == 0) g_mask_u8 = f;
    }

    int d4 = blockIdx.x * 128 + t;      // float4 index in [0,256)
    int ks = blockIdx.y;
    int b  = blockIdx.z;
    const float4* p = reinterpret_cast<const float4*>(u)
                    + ((size_t)(b * Kk + ks * 128)) * 256 + d4;
    float4 s = make_float4(0.f, 0.f, 0.f, 0.f);
#pragma unroll 8
    for (int k = 0; k < 128; k++) {
        float4 v = p[(size_t)k * 256];
        s.x += v.x; s.y += v.y; s.z += v.z; s.w += v.w;
    }
    reinterpret_cast<float4*>(g_UsumP)[(b * 8 + ks) * 256 + d4] = s;
}

// ---------------------------------------------------------------------------
// K2: v0 = squash((1/6) * Usum . W).  grid (O, B), 512 threads.
// ---------------------------------------------------------------------------
__global__ __launch_bounds__(512) void k_v0(const float* __restrict__ W) {
    int t = threadIdx.x;
    int o = blockIdx.x, b = blockIdx.y;
    __shared__ float Us[Dd];
    __shared__ float part[4][Ee];
    __shared__ float red[4];

    for (int d = t; d < Dd; d += 512) {
        float s = 0.f;
#pragma unroll
        for (int ks = 0; ks < 8; ks++) s += g_UsumP[(b * 8 + ks) * Dd + d];
        Us[d] = s;
    }
    __syncthreads();

    int e = t & 127, ws = t >> 7;
    const float* Wp = W + (size_t)o * Dd * Ee + e;
    float acc = 0.f;
#pragma unroll 16
    for (int dd = 0; dd < 256; dd++) {
        int d = ws * 256 + dd;
        acc += Us[d] * Wp[(size_t)d * Ee];
    }
    part[ws][e] = acc;
    __syncthreads();

    float v = 0.f;
    if (t < 128) {
        float s = (part[0][t] + part[1][t] + part[2][t] + part[3][t]) * (1.f / 6.f);
        v = s;
        float x = s * s;
#pragma unroll
        for (int sh = 16; sh; sh >>= 1) x += __shfl_xor_sync(0xffffffffu, x, sh);
        if ((t & 31) == 0) red[t >> 5] = x;
    }
    __syncthreads();
    if (t < 128) {
        float sq = red[0] + red[1] + red[2] + red[3];
        float f  = sq / (1.f + sq) / (sqrtf(sq) + 1e-8f);
        g_Vacc[(b * Oo + o) * Ee + t] = f * v;   // Vacc starts as v0
    }
}

// ---------------------------------------------------------------------------
// K3: Wv[b,o,d] = sum_e W[o,d,e] * Vacc[b,o,e].
// grid (Dd/8=128, Oo), 256 threads = 8 warps, warp w owns d = bx*8+w.
// Coalesced float4 W row per warp; all 8 b amortized from smem.
// ---------------------------------------------------------------------------
__global__ __launch_bounds__(256) void k_wv(const float* __restrict__ W) {
    __shared__ float4 Vs[Bb][32];      // Vacc[b][o][e] for this o: 4 KB
    int t = threadIdx.x, w = t >> 5, lane = t & 31;
    int o = blockIdx.y;

    {
        int b = t >> 5, i = t & 31;    // 256 threads = exactly 8*32
        Vs[b][i] = reinterpret_cast<const float4*>(g_Vacc)[(b * Oo + o) * 32 + i];
    }
    __syncthreads();

    int d = blockIdx.x * 8 + w;
    float4 w4 = reinterpret_cast<const float4*>(W)[((size_t)o * Dd + d) * 32 + lane];

    float acc[8];
#pragma unroll
    for (int b = 0; b < 8; b++) {
        float4 v4 = Vs[b][lane];
        acc[b] = w4.x * v4.x + w4.y * v4.y + w4.z * v4.z + w4.w * v4.w;
    }
#pragma unroll
    for (int sh = 16; sh; sh >>= 1) {
#pragma unroll
        for (int b = 0; b < 8; b++)
            acc[b] += __shfl_xor_sync(0xffffffffu, acc[b], sh);
    }
    if (lane < 8)
        g_Wv[(lane * Oo + o) * Dd + d] = acc[lane];   // b = lane
}

// ---------------------------------------------------------------------------
// K4: fused logits -> softmax(masked) -> probs -> Up partials (float4).
// grid (K/32=32, B), 256 threads = 8 warps, each warp owns 4 k rows.
// ---------------------------------------------------------------------------
__global__ __launch_bounds__(256) void k_route(const float* __restrict__ u,
                                               const void*  __restrict__ maskp) {
    int t = threadIdx.x;
    int w = t >> 5, lane = t & 31;
    int b  = blockIdx.y;
    int k0 = blockIdx.x * 32;

    __shared__ __align__(16) float Wv_s[Oo * Dd];   // 24 KB
    __shared__ float probs_s[32 * Oo];

    {
        float4*       ds = reinterpret_cast<float4*>(Wv_s);
        const float4* ss = reinterpret_cast<const float4*>(g_Wv + (size_t)b * Oo * Dd);
#pragma unroll
        for (int i = 0; i < 6; i++) ds[t + 256 * i] = ss[t + 256 * i];
    }
    __syncthreads();

    // Phase 1: logits for 4 k per warp, float4 over d
    int kw = k0 + w * 4;
    float lg[4][6];
#pragma unroll
    for (int kk = 0; kk < 4; kk++)
#pragma unroll
        for (int o = 0; o < 6; o++) lg[kk][o] = 0.f;

    const float4* up4 = reinterpret_cast<const float4*>(u) + (size_t)(b * Kk + kw) * 256;
    const float4* wv4 = reinterpret_cast<const float4*>(Wv_s);
#pragma unroll
    for (int j = 0; j < 8; j++) {
        int di = j * 32 + lane;                 // float4 index within a d-row
        float4 wv[6];
#pragma unroll
        for (int o = 0; o < 6; o++) wv[o] = wv4[o * 256 + di];
#pragma unroll
        for (int kk = 0; kk < 4; kk++) {
            float4 uv = up4[(size_t)kk * 256 + di];
#pragma unroll
            for (int o = 0; o < 6; o++)
                lg[kk][o] += uv.x * wv[o].x + uv.y * wv[o].y
                           + uv.z * wv[o].z + uv.w * wv[o].w;
        }
    }
#pragma unroll
    for (int sh = 16; sh; sh >>= 1)
#pragma unroll
        for (int kk = 0; kk < 4; kk++)
#pragma unroll
            for (int o = 0; o < 6; o++)
                lg[kk][o] += __shfl_xor_sync(0xffffffffu, lg[kk][o], sh);

    int u8 = g_mask_u8;
    if (lane == 0) {
#pragma unroll
        for (int kk = 0; kk < 4; kk++) {
            int k = kw + kk;
            bool masked = u8 ? (((const unsigned char*)maskp)[b * Kk + k] != 0)
                             : (((const int*)maskp)[b * Kk + k] != 0);
            float p[6];
            if (masked) {
#pragma unroll
                for (int o = 0; o < 6; o++) p[o] = 1.f / 6.f;
            } else {
                float m = lg[kk][0];
#pragma unroll
                for (int o = 1; o < 6; o++) m = fmaxf(m, lg[kk][o]);
                float s = 0.f;
#pragma unroll
                for (int o = 0; o < 6; o++) { p[o] = expf(lg[kk][o] - m); s += p[o]; }
                float inv = 1.f / s;
#pragma unroll
                for (int o = 0; o < 6; o++) p[o] *= inv;
            }
#pragma unroll
            for (int o = 0; o < 6; o++) probs_s[(w * 4 + kk) * 6 + o] = p[o];
        }
    }
    __syncthreads();

    // coalesced probs store (32 k * 6 o = 192 floats)
    if (t < 192) g_probs[(size_t)(b * Kk + k0) * 6 + t] = probs_s[t];

    // Phase 2: Up partials — thread owns float4 d-chunk d4 = t (1024 d total)
    float4 acc4[6];
#pragma unroll
    for (int o = 0; o < 6; o++) acc4[o] = make_float4(0.f, 0.f, 0.f, 0.f);

    const float4* ub4 = reinterpret_cast<const float4*>(u) + (size_t)(b * Kk + k0) * 256;
#pragma unroll 4
    for (int kk = 0; kk < 32; kk++) {
        float4 uv = ub4[(size_t)kk * 256 + t];
        float pv[6];
#pragma unroll
        for (int o = 0; o < 6; o++) pv[o] = probs_s[kk * 6 + o];
#pragma unroll
        for (int o = 0; o < 6; o++) {
            acc4[o].x += pv[o] * uv.x;
            acc4[o].y += pv[o] * uv.y;
            acc4[o].z += pv[o] * uv.z;
            acc4[o].w += pv[o] * uv.w;
        }
    }
    float4* upp4 = reinterpret_cast<float4*>(
        g_UpP + ((size_t)(b * 32 + blockIdx.x) * Oo) * Dd);
#pragma unroll
    for (int o = 0; o < 6; o++) upp4[o * 256 + t] = acc4[o];
}

// ---------------------------------------------------------------------------
// K6: v_i = squash(Up . W); Vacc += v_i; store v_i.  grid (O, B), 512 threads.
// ---------------------------------------------------------------------------
__global__ __launch_bounds__(512) void k_vi(const float* __restrict__ W) {
    int t = threadIdx.x;
    int o = blockIdx.x, b = blockIdx.y;
    __shared__ float Up_s[Dd];
    __shared__ float part[4][Ee];
    __shared__ float red[4];

    for (int d = t; d < Dd; d += 512) {
        float s = 0.f;
#pragma unroll 8
        for (int kt = 0; kt < 32; kt++)
            s += g_UpP[((size_t)(b * 32 + kt) * Oo + o) * Dd + d];
        Up_s[d] = s;
    }
    __syncthreads();

    int e = t & 127, ws = t >> 7;
    const float* Wp = W + (size_t)o * Dd * Ee + e;
    float acc = 0.f;
#pragma unroll 16
    for (int dd = 0; dd < 256; dd++) {
        int d = ws * 256 + dd;
        acc += Up_s[d] * Wp[(size_t)d * Ee];
    }
    part[ws][e] = acc;
    __syncthreads();

    float v = 0.f;
    if (t < 128) {
        float s = part[0][t] + part[1][t] + part[2][t] + part[3][t];
        v = s;
        float x = s * s;
#pragma unroll
        for (int sh = 16; sh; sh >>= 1) x += __shfl_xor_sync(0xffffffffu, x, sh);
        if ((t & 31) == 0) red[t >> 5] = x;
    }
    __syncthreads();
    if (t < 128) {
        float sq = red[0] + red[1] + red[2] + red[3];
        float f  = sq / (1.f + sq) / (sqrtf(sq) + 1e-8f);
        float vv = f * v;
        int idx = (b * Oo + o) * Ee + t;
        g_vcur[idx] = vv;
        g_Vacc[idx] += vv;
    }
}

// ---------------------------------------------------------------------------
// K7 (REWRITTEN): broadcast over L with register staging + streaming stores.
// out = [outputs_v (B,L,O,E) | probs_c (B,L,K,O)].
// grid = B * L/8 = 1024 blocks, 256 threads. Each block loads its b-source
// ONCE into registers (6 probs float4/thread + 1 v float4 for t<192), then
// writes 8 l replicas with coalesced __stcs. L2 read traffic: 226MB -> 28MB.
// ---------------------------------------------------------------------------
__global__ __launch_bounds__(256) void k_bcast(float* __restrict__ out) {
    int t   = threadIdx.x;
    int blk = blockIdx.x;              // b * 128 + l-chunk
    int b   = blk >> 7;
    int l0  = (blk & 127) * 8;

    const float4* ps = reinterpret_cast<const float4*>(g_probs) + (size_t)b * 1536;
    float4 pr[6];
#pragma unroll
    for (int i = 0; i < 6; i++) pr[i] = __ldg(ps + t + 256 * i);

    float4 vv;
    if (t < 192)
        vv = __ldg(reinterpret_cast<const float4*>(g_vcur) + b * 192 + t);

    float4* ov = reinterpret_cast<float4*>(out);
    float4* op = reinterpret_cast<float4*>(out + (size_t)Bb * Ll * Oo * Ee);

#pragma unroll
    for (int j = 0; j < 8; j++) {
        size_t bl = (size_t)b * Ll + l0 + j;
        if (t < 192) __stcs(ov + bl * 192 + t, vv);       // 768 floats
#pragma unroll
        for (int i = 0; i < 6; i++)                       // 6144 floats
            __stcs(op + bl * 1536 + t + 256 * i, pr[i]);
    }
}

// ---------------------------------------------------------------------------
// Launch
// ---------------------------------------------------------------------------
extern "C" void kernel_launch(void* const* d_in, const int* in_sizes, int n_in,
                              void* d_out, int out_size) {
    const float* u    = (const float*)d_in[0];
    // d_in[1] = context_sequence: unused (only its shape L matters)
    const float* W    = (const float*)d_in[2];
    const void*  mask = d_in[3];
    float* out = (float*)d_out;

    k_usum<<<dim3(2, 8, 8), 128>>>(u, (const unsigned char*)mask);
    k_v0  <<<dim3(Oo, Bb), 512>>>(W);

    for (int it = 0; it < 2; it++) {
        k_wv   <<<dim3(Dd / 8, Oo), 256>>>(W);
        k_route<<<dim3(Kk / 32, Bb), 256>>>(u, mask);
        k_vi   <<<dim3(Oo, Bb), 512>>>(W);
    }

    k_bcast<<<Bb * (Ll / 8), 256>>>(out);
}